// round 16
// baseline (speedup 1.0000x reference)
#include <cuda_runtime.h>
#include <cuda_bf16.h>
#include <math.h>
#include <stdint.h>

#define Bb 32
#define Tt 512
#define Dd 512
#define Hh 2048
#define H3 6144
#define Pp 1024
#define MT (Bb*Tt)   // 16384
#define GRID_SCAN 128

typedef unsigned long long ull;

// ---------------- scratch ----------------------------------------------------------
__device__ float g_A1[(size_t)MT * 1024];
__device__ float g_A2[(size_t)MT * Hh];
__device__ float g_GI[(size_t)MT * H3];               // gi row-major (M,3H), r=b*T+t
__device__ float g_HS[(size_t)MT * Hh];               // h history ROW-MAJOR r=t*32+b
__device__ float g_S [(size_t)MT * Pp];
// W_hh fragment-packed: [blk(128)][nf(6)][chunk(128)][lane(32)][4 regs] + pad
__device__ __align__(256) uint32_t g_WF[(size_t)128 * 6 * 128 * 128 + 1024];
// h fragment ping-pong: [chunk(128)][frag(2)][hi 128 u32 | lo 128 u32] + pad
__device__ __align__(256) uint32_t g_HF[2][128 * 512 + 8 * 512];
__device__ volatile unsigned g_flags[GRID_SCAN];
__device__ volatile unsigned g_release;

// ---------------- helpers ----------------------------------------------------------
__device__ __forceinline__ float sigm(float x) { return 1.f / (1.f + expf(-x)); }
__device__ __forceinline__ uint32_t smem_u32(const void* p) {
    uint32_t a;
    asm("{ .reg .u64 t; cvta.to.shared.u64 t, %1; cvt.u32.u64 %0, t; }" : "=r"(a) : "l"(p));
    return a;
}
__device__ __forceinline__ void ldsm_x4(uint32_t* r, uint32_t addr) {
    asm volatile("ldmatrix.sync.aligned.m8n8.x4.shared.b16 {%0,%1,%2,%3}, [%4];"
                 : "=r"(r[0]), "=r"(r[1]), "=r"(r[2]), "=r"(r[3]) : "r"(addr));
}
__device__ __forceinline__ void ldsm_x2(uint32_t* r, uint32_t addr) {
    asm volatile("ldmatrix.sync.aligned.m8n8.x2.shared.b16 {%0,%1}, [%2];"
                 : "=r"(r[0]), "=r"(r[1]) : "r"(addr));
}
__device__ __forceinline__ void mma_bf16(float* c, const uint32_t* a, const uint32_t* b) {
    asm volatile("mma.sync.aligned.m16n8k16.row.col.f32.bf16.bf16.f32 "
                 "{%0,%1,%2,%3}, {%4,%5,%6,%7}, {%8,%9}, {%0,%1,%2,%3};"
                 : "+f"(c[0]), "+f"(c[1]), "+f"(c[2]), "+f"(c[3])
                 : "r"(a[0]), "r"(a[1]), "r"(a[2]), "r"(a[3]), "r"(b[0]), "r"(b[1]));
}
__device__ __forceinline__ void cvt_hilo(float x, float y, uint32_t& hi, uint32_t& lo) {
    __nv_bfloat16 hx = __float2bfloat16(x), hy = __float2bfloat16(y);
    float lx = x - __bfloat162float(hx), ly = y - __bfloat162float(hy);
    __nv_bfloat162 ph = __halves2bfloat162(hx, hy);
    __nv_bfloat162 pl = __halves2bfloat162(__float2bfloat16(lx), __float2bfloat16(ly));
    hi = *reinterpret_cast<uint32_t*>(&ph);
    lo = *reinterpret_cast<uint32_t*>(&pl);
}
__device__ __forceinline__ unsigned ld_acq(volatile unsigned* p) {
    unsigned v;
    asm volatile("ld.global.acquire.gpu.b32 %0, [%1];" : "=r"(v) : "l"((unsigned*)p));
    return v;
}
__device__ __forceinline__ void st_rel(volatile unsigned* p, unsigned v) {
    asm volatile("st.global.release.gpu.b32 [%0], %1;" :: "l"((unsigned*)p), "r"(v));
}

// ---------------- split-bf16 mma.sync GEMM (proven R12/R13) ------------------------
#define MMROW 48
#define MMSTG 24576
__global__ __launch_bounds__(256)
void mma_gemm(const float* __restrict__ A, const float* __restrict__ B,
              const float* __restrict__ bias, float* __restrict__ C,
              int M, int N, int K, int doRelu)
{
    extern __shared__ char sm[];
    const uint32_t sbase = smem_u32(sm);
    const int tid  = threadIdx.x;
    const int wid  = tid >> 5;
    const int lane = tid & 31;
    const int wm   = wid & 1;
    const int wn   = wid >> 1;
    const int mb   = blockIdx.y, nb = blockIdx.x;

    const int srow = tid >> 2;
    const int scol = (tid & 3) * 4;
    const float* Ag = A + (size_t)(mb * 128 + srow) * K + scol;
    const float* Bg = B + (size_t)(nb * 128 + srow) * K + scol;
    const size_t g64 = (size_t)64 * K;

    float c[4][4][4];
#pragma unroll
    for (int i = 0; i < 4; i++)
#pragma unroll
        for (int j = 0; j < 4; j++)
#pragma unroll
            for (int q = 0; q < 4; q++) c[i][j][q] = 0.f;

    const int nk = K >> 4;
    float4 ra0, ra1, rb0, rb1;
    ra0 = *(const float4*)(Ag); ra1 = *(const float4*)(Ag + g64);
    rb0 = *(const float4*)(Bg); rb1 = *(const float4*)(Bg + g64);

    int buf = 0;
#define STORE_STAGE(BUF)                                                          \
    {                                                                             \
        uint32_t off = (BUF) * MMSTG;                                             \
        uint32_t h, l;                                                            \
        uint32_t a0 = off + srow * MMROW + scol * 2;                              \
        cvt_hilo(ra0.x, ra0.y, h, l);                                             \
        *(uint32_t*)(sm + a0)        = h; *(uint32_t*)(sm + a0 + 6144)     = l;   \
        cvt_hilo(ra0.z, ra0.w, h, l);                                             \
        *(uint32_t*)(sm + a0 + 4)    = h; *(uint32_t*)(sm + a0 + 6148)     = l;   \
        uint32_t a1 = a0 + 64 * MMROW;                                            \
        cvt_hilo(ra1.x, ra1.y, h, l);                                             \
        *(uint32_t*)(sm + a1)        = h; *(uint32_t*)(sm + a1 + 6144)     = l;   \
        cvt_hilo(ra1.z, ra1.w, h, l);                                             \
        *(uint32_t*)(sm + a1 + 4)    = h; *(uint32_t*)(sm + a1 + 6148)     = l;   \
        uint32_t b0 = off + 12288 + srow * MMROW + scol * 2;                      \
        cvt_hilo(rb0.x, rb0.y, h, l);                                             \
        *(uint32_t*)(sm + b0)        = h; *(uint32_t*)(sm + b0 + 6144)     = l;   \
        cvt_hilo(rb0.z, rb0.w, h, l);                                             \
        *(uint32_t*)(sm + b0 + 4)    = h; *(uint32_t*)(sm + b0 + 6148)     = l;   \
        uint32_t b1 = b0 + 64 * MMROW;                                            \
        cvt_hilo(rb1.x, rb1.y, h, l);                                             \
        *(uint32_t*)(sm + b1)        = h; *(uint32_t*)(sm + b1 + 6144)     = l;   \
        cvt_hilo(rb1.z, rb1.w, h, l);                                             \
        *(uint32_t*)(sm + b1 + 4)    = h; *(uint32_t*)(sm + b1 + 6148)     = l;   \
    }

    STORE_STAGE(0);
    __syncthreads();

    const uint32_t a_lrow = (uint32_t)(wm * 64 + (lane & 15)) * MMROW + ((lane >> 4) * 16);
    const uint32_t b_lrow = (uint32_t)(wn * 32 + (lane & 7)) * MMROW + (((lane >> 3) & 1) * 16);

    for (int kt = 0; kt < nk; kt++) {
        if (kt + 1 < nk) {
            const float* Agn = Ag + (kt + 1) * 16;
            const float* Bgn = Bg + (kt + 1) * 16;
            ra0 = *(const float4*)(Agn); ra1 = *(const float4*)(Agn + g64);
            rb0 = *(const float4*)(Bgn); rb1 = *(const float4*)(Bgn + g64);
        }
        const uint32_t off = buf * MMSTG;
        uint32_t ahi[4][4], alo[4][4];
#pragma unroll
        for (int mf = 0; mf < 4; mf++) {
            uint32_t ad = sbase + off + a_lrow + (uint32_t)mf * 16 * MMROW;
            ldsm_x4(ahi[mf], ad);
            ldsm_x4(alo[mf], ad + 6144);
        }
#pragma unroll
        for (int nf = 0; nf < 4; nf++) {
            uint32_t bd = sbase + off + 12288 + b_lrow + (uint32_t)nf * 8 * MMROW;
            uint32_t bhi[2], blo[2];
            ldsm_x2(bhi, bd);
            ldsm_x2(blo, bd + 6144);
#pragma unroll
            for (int mf = 0; mf < 4; mf++) {
                mma_bf16(c[mf][nf], ahi[mf], bhi);
                mma_bf16(c[mf][nf], ahi[mf], blo);
                mma_bf16(c[mf][nf], alo[mf], bhi);
            }
        }
        if (kt + 1 < nk) {
            STORE_STAGE(buf ^ 1);
            __syncthreads();
            buf ^= 1;
        }
    }
#undef STORE_STAGE

    const int rbase = mb * 128 + wm * 64 + (lane >> 2);
    const int cbase = nb * 128 + wn * 32 + 2 * (lane & 3);
#pragma unroll
    for (int mf = 0; mf < 4; mf++) {
#pragma unroll
        for (int nf = 0; nf < 4; nf++) {
            int col = cbase + nf * 8;
            float b0 = bias[col], b1 = bias[col + 1];
            float v0 = c[mf][nf][0] + b0, v1 = c[mf][nf][1] + b1;
            float v2 = c[mf][nf][2] + b0, v3 = c[mf][nf][3] + b1;
            if (doRelu) {
                v0 = fmaxf(v0, 0.f); v1 = fmaxf(v1, 0.f);
                v2 = fmaxf(v2, 0.f); v3 = fmaxf(v3, 0.f);
            }
            int r0 = rbase + mf * 16;
            *(float2*)(C + (size_t)r0 * N + col)       = make_float2(v0, v1);
            *(float2*)(C + (size_t)(r0 + 8) * N + col) = make_float2(v2, v3);
        }
    }
}

// ---------------- prepack W_hh into B-fragment stream ------------------------------
__global__ __launch_bounds__(256)
void prepack_wf(const float* __restrict__ Whh, uint32_t* __restrict__ WF)
{
    int gw = blockIdx.x * 8 + (threadIdx.x >> 5);   // 0 .. 98303
    int lane = threadIdx.x & 31;
    int chunk = gw & 127;
    int rest  = gw >> 7;
    int nf  = rest % 6;
    int blk = rest / 6;
    int g   = nf >> 1;
    int n   = g * Hh + blk * 16 + (nf & 1) * 8 + (lane >> 2);
    int k   = chunk * 16 + 2 * (lane & 3);
    const float* wr = Whh + (size_t)n * Hh + k;
    uint32_t bh0, bl0, bh1, bl1;
    cvt_hilo(wr[0], wr[1], bh0, bl0);
    cvt_hilo(wr[8], wr[9], bh1, bl1);
    uint32_t* o = WF + ((size_t)gw) * 128 + lane * 4;
    o[0] = bh0; o[1] = bh1; o[2] = bl0; o[3] = bl1;
}

// ---------------- prepack h0 into A-fragment stream --------------------------------
__global__ __launch_bounds__(256)
void prepack_hf0(const float* __restrict__ h0, uint32_t* __restrict__ HF0)
{
    int gw = blockIdx.x * 8 + (threadIdx.x >> 5);   // 0..255
    int lane = threadIdx.x & 31;
    int c = gw >> 1, f = gw & 1;
    int b = f * 16 + (lane >> 2);
    int k = c * 16 + 2 * (lane & 3);
    const float* p0 = h0 + (size_t)b * Hh + k;
    const float* p1 = h0 + (size_t)(b + 8) * Hh + k;
    uint32_t h0r, l0r, h1r, l1r, h2r, l2r, h3r, l3r;
    cvt_hilo(p0[0], p0[1], h0r, l0r);
    cvt_hilo(p1[0], p1[1], h1r, l1r);
    cvt_hilo(p0[8], p0[9], h2r, l2r);
    cvt_hilo(p1[8], p1[9], h3r, l3r);
    uint32_t* o = HF0 + c * 512 + f * 256 + lane * 4;
    o[0] = h0r; o[1] = h1r; o[2] = h2r; o[3] = h3r;
    o[128] = l0r; o[129] = l1r; o[130] = l2r; o[131] = l3r;
}

__global__ void reset_bar()
{
    int i = threadIdx.x;
    if (i < GRID_SCAN) g_flags[i] = 0u;
    if (i == 0) g_release = 0u;
}

// ---------------- persistent mma GRU scan (R15 core + fast tail) -------------------
// 128 blocks x 384 threads (12 warps = 6 nfrags x 2 khalves). Block = 16 hcols x 3 gates.
__global__ __launch_bounds__(384, 1)
void gru_scan(const float* __restrict__ gi0,     // row-major (M,3H), r=b*T+t
              const float* __restrict__ h0,      // (B, H)
              const uint32_t* __restrict__ WF,   // packed weights
              const float* __restrict__ bhh,
              float* __restrict__ HSrm,          // (M, H), r=t*32+b
              uint32_t* __restrict__ HFa,        // h frag ping-pong
              uint32_t* __restrict__ HFb)
{
    __shared__ float sred[2][6][32][8];           // 12 KB
    __shared__ uint32_t hfst[512];                // 2 KB h-frag staging

    const int tid  = threadIdx.x;
    const int w    = tid >> 5;
    const int lane = tid & 31;
    const int nf   = w % 6;
    const int kh   = w / 6;
    const int blk  = blockIdx.x;
    const int ch0  = kh * 64;

    const uint32_t* wstream = WF + ((size_t)(blk * 6 + nf) * 128 + ch0) * 128 + lane * 4;

    const int ecol = tid >> 4;         // 0..15 (tid<256)
    const int ebp  = tid & 15;
    const int colg = blk * 16 + ecol;
    float br = 0.f, bz = 0.f, bn = 0.f;
    if (tid < 256) { br = bhh[colg]; bz = bhh[Hh + colg]; bn = bhh[2 * Hh + colg]; }

    for (int t = 0; t < Tt; t++) {
        const uint32_t* HFc = ((t & 1) ? HFb : HFa) + lane * 4;
        uint32_t*       HFn = (t & 1) ? HFa : HFb;

        // early epilogue-operand prefetch (consumed after the mainloop)
        float gi_r0 = 0.f, gi_r1 = 0.f, gi_z0 = 0.f, gi_z1 = 0.f;
        float gi_n0 = 0.f, gi_n1 = 0.f, hv0 = 0.f, hv1 = 0.f;
        if (tid < 256) {
            const int b0 = 2 * ebp, b1 = b0 + 1;
            const float* gr0 = gi0 + ((size_t)b0 * Tt + t) * H3 + colg;
            const float* gr1 = gi0 + ((size_t)b1 * Tt + t) * H3 + colg;
            gi_r0 = gr0[0];      gi_r1 = gr1[0];
            gi_z0 = gr0[Hh];     gi_z1 = gr1[Hh];
            gi_n0 = gr0[2 * Hh]; gi_n1 = gr1[2 * Hh];
            const float* hp0 = (t == 0) ? (h0 + (size_t)b0 * Hh)
                                        : (HSrm + ((size_t)(t - 1) * 32 + b0) * Hh);
            const float* hp1 = (t == 0) ? (h0 + (size_t)b1 * Hh)
                                        : (HSrm + ((size_t)(t - 1) * 32 + b1) * Hh);
            hv0 = hp0[colg]; hv1 = hp1[colg];
        }

        float c0[4] = {0.f, 0.f, 0.f, 0.f};
        float c1[4] = {0.f, 0.f, 0.f, 0.f};

        // rings: h depth 4 (4 x uint4), weights depth 8 (1 x uint4)
        uint4 rh[4][4];
        uint4 rw[8];
#pragma unroll
        for (int s = 0; s < 4; s++) {
            rh[s][0] = *(const uint4*)(HFc + (ch0 + s) * 512);
            rh[s][1] = *(const uint4*)(HFc + (ch0 + s) * 512 + 128);
            rh[s][2] = *(const uint4*)(HFc + (ch0 + s) * 512 + 256);
            rh[s][3] = *(const uint4*)(HFc + (ch0 + s) * 512 + 384);
        }
#pragma unroll
        for (int s = 0; s < 8; s++)
            rw[s] = *(const uint4*)(wstream + (size_t)s * 128);

        for (int c = 0; c < 64; c += 8) {
#pragma unroll
            for (int u = 0; u < 8; u++) {
                const int hu = u & 3;
                uint4 ah0 = rh[hu][0], al0 = rh[hu][1];
                uint4 ah1 = rh[hu][2], al1 = rh[hu][3];
                uint4 bq  = rw[u];
                const int cnh = c + u + 4;
                const int cnw = c + u + 8;
                rh[hu][0] = *(const uint4*)(HFc + (ch0 + cnh) * 512);
                rh[hu][1] = *(const uint4*)(HFc + (ch0 + cnh) * 512 + 128);
                rh[hu][2] = *(const uint4*)(HFc + (ch0 + cnh) * 512 + 256);
                rh[hu][3] = *(const uint4*)(HFc + (ch0 + cnh) * 512 + 384);
                rw[u] = *(const uint4*)(wstream + (size_t)cnw * 128);

                uint32_t bh[2] = {bq.x, bq.y};
                uint32_t bl[2] = {bq.z, bq.w};
                mma_bf16(c0, (const uint32_t*)&ah0, bh);
                mma_bf16(c0, (const uint32_t*)&ah0, bl);
                mma_bf16(c0, (const uint32_t*)&al0, bh);
                mma_bf16(c1, (const uint32_t*)&ah1, bh);
                mma_bf16(c1, (const uint32_t*)&ah1, bl);
                mma_bf16(c1, (const uint32_t*)&al1, bh);
            }
        }

        // store C fragments: rows = batches, cols = n within frag
        {
            float* sp = &sred[kh][nf][0][0];
            int r = lane >> 2, cb = 2 * (lane & 3);
            sp[r * 8 + cb]            = c0[0];
            sp[r * 8 + cb + 1]        = c0[1];
            sp[(r + 8) * 8 + cb]      = c0[2];
            sp[(r + 8) * 8 + cb + 1]  = c0[3];
            sp[(r + 16) * 8 + cb]     = c1[0];
            sp[(r + 16) * 8 + cb + 1] = c1[1];
            sp[(r + 24) * 8 + cb]     = c1[2];
            sp[(r + 24) * 8 + cb + 1] = c1[3];
        }
        __syncthreads();

        if (tid < 256) {
            const int jj = ecol;
            const int nn = jj & 7;
            const int b0 = 2 * ebp, b1 = b0 + 1;
            const int nfr = (jj >> 3);
            float ghr0 = sred[0][0 + nfr][b0][nn] + sred[1][0 + nfr][b0][nn];
            float ghr1 = sred[0][0 + nfr][b1][nn] + sred[1][0 + nfr][b1][nn];
            float ghz0 = sred[0][2 + nfr][b0][nn] + sred[1][2 + nfr][b0][nn];
            float ghz1 = sred[0][2 + nfr][b1][nn] + sred[1][2 + nfr][b1][nn];
            float ghn0 = sred[0][4 + nfr][b0][nn] + sred[1][4 + nfr][b0][nn];
            float ghn1 = sred[0][4 + nfr][b1][nn] + sred[1][4 + nfr][b1][nn];

            float rx = sigm(gi_r0 + ghr0 + br);
            float ry = sigm(gi_r1 + ghr1 + br);
            float zx = sigm(gi_z0 + ghz0 + bz);
            float zy = sigm(gi_z1 + ghz1 + bz);
            float nx = tanhf(gi_n0 + rx * (ghn0 + bn));
            float ny = tanhf(gi_n1 + ry * (ghn1 + bn));
            float hn0 = (1.f - zx) * nx + zx * hv0;
            float hn1 = (1.f - zy) * ny + zy * hv1;

            HSrm[((size_t)t * 32 + b0) * Hh + colg] = hn0;
            HSrm[((size_t)t * 32 + b1) * Hh + colg] = hn1;

            // stage h fragments into smem (same layout as global chunk)
            const int kk = colg & 15;
            const int lidx = ((kk >> 1) & 3);
#pragma unroll
            for (int bi = 0; bi < 2; bi++) {
                int b = b0 + bi;
                float hv = bi ? hn1 : hn0;
                int f = b >> 4, r = b & 15;
                int ln = ((r & 7) << 2) | lidx;
                int rg = ((r >> 3) & 1) | (((kk >> 3) & 1) << 1);
                int idx_hi = f * 256 + ln * 4 + rg;
                __nv_bfloat16 hh = __float2bfloat16(hv);
                __nv_bfloat16 hl = __float2bfloat16(hv - __bfloat162float(hh));
                ((__nv_bfloat16*)hfst)[2 * idx_hi + (kk & 1)]         = hh;
                ((__nv_bfloat16*)hfst)[2 * (idx_hi + 128) + (kk & 1)] = hl;
            }
        }
        __syncthreads();

        // coalesced flush: whole block owns HF chunk == blk (2 KB = 128 uint4)
        if (tid < 128) {
            ((uint4*)(HFn + (size_t)blk * 512))[tid] = ((const uint4*)hfst)[tid];
        }

        // -------- grid sync (flag array + single release word) --------
        __syncthreads();
        const unsigned want = (unsigned)(t + 1);
        if (tid == 0) {
            __threadfence();
            st_rel(&g_flags[blk], want);
        }
        if (blk == 0) {
            if (tid < GRID_SCAN) {
                while (ld_acq(&g_flags[tid]) < want) __nanosleep(32);
            }
            __syncthreads();
            if (tid == 0) { __threadfence(); st_rel(&g_release, want); }
        }
        if (tid == 0) {
            while (ld_acq(&g_release) < want) __nanosleep(32);
        }
        __syncthreads();
    }
}

// ---------------- head --------------------------------------------------------------
__global__ __launch_bounds__(256)
void head_kernel(const float* __restrict__ S, const float* __restrict__ Wp,
                 const float* __restrict__ bp, const int* __restrict__ label,
                 float* __restrict__ out)
{
    int w    = blockIdx.x * 8 + (threadIdx.x >> 5);
    int lane = threadIdx.x & 31;
    int bt = w / 3, j = w % 3;
    int t = bt >> 5, b = bt & 31;        // S row = t*32 + b
    int lab = label[b];
    const float* sp = S  + (size_t)bt * Pp;
    const float* wp = Wp + (size_t)(j * 8 + lab) * Pp;
    float sum = 0.f;
    for (int d = lane; d < Pp; d += 32)
        sum = fmaf(sp[d], wp[d], sum);
#pragma unroll
    for (int o = 16; o > 0; o >>= 1) sum += __shfl_xor_sync(0xffffffffu, sum, o);
    if (lane == 0)
        out[(size_t)b * Tt * 3 + t * 3 + j] = sum + bp[j * 8 + lab];
}

__global__ void copy_hlast(const float* __restrict__ HSrm, float* __restrict__ dst)
{
    int i = blockIdx.x * 256 + threadIdx.x;   // i = b*Hh + c
    if (i < Bb * Hh) {
        int b = i >> 11, c = i & (Hh - 1);
        dst[i] = HSrm[((size_t)(Tt - 1) * 32 + b) * Hh + c];
    }
}

// ---------------- launch ------------------------------------------------------------
extern "C" void kernel_launch(void* const* d_in, const int* in_sizes, int n_in,
                              void* d_out, int out_size)
{
    (void)in_sizes; (void)n_in; (void)out_size;
    const float* x     = (const float*)d_in[0];
    const int*   label = (const int*)  d_in[1];
    const float* h0    = (const float*)d_in[2];
    const float* W1  = (const float*)d_in[3];  const float* b1  = (const float*)d_in[4];
    const float* W2  = (const float*)d_in[5];  const float* b2  = (const float*)d_in[6];
    const float* Wih = (const float*)d_in[7];  const float* bih = (const float*)d_in[8];
    const float* Whh = (const float*)d_in[9];  const float* bhh = (const float*)d_in[10];
    const float* W3  = (const float*)d_in[11]; const float* b3  = (const float*)d_in[12];
    const float* Wp  = (const float*)d_in[13]; const float* bp  = (const float*)d_in[14];
    float* out = (float*)d_out;

    float *A1, *A2, *GI, *HS, *S;
    uint32_t *WF, *HF;
    cudaGetSymbolAddress((void**)&A1, g_A1);
    cudaGetSymbolAddress((void**)&A2, g_A2);
    cudaGetSymbolAddress((void**)&GI, g_GI);
    cudaGetSymbolAddress((void**)&HS, g_HS);
    cudaGetSymbolAddress((void**)&S,  g_S);
    cudaGetSymbolAddress((void**)&WF, g_WF);
    cudaGetSymbolAddress((void**)&HF, g_HF);
    uint32_t* HFa = HF;
    uint32_t* HFb = HF + (128 * 512 + 8 * 512);

    prepack_wf<<<98304 / 8, 256>>>(Whh, WF);
    prepack_hf0<<<256 / 8, 256>>>(h0, HFa);
    reset_bar<<<1, 128>>>();

    // all four big GEMMs on tensor cores (split-bf16, 3 passes)
    mma_gemm<<<dim3(1024 / 128, MT / 128), 256, 2 * MMSTG>>>(x,  W1, b1, A1, MT, 1024, Dd, 1);
    mma_gemm<<<dim3(Hh   / 128, MT / 128), 256, 2 * MMSTG>>>(A1, W2, b2, A2, MT, Hh, 1024, 1);
    mma_gemm<<<dim3(H3   / 128, MT / 128), 256, 2 * MMSTG>>>(A2, Wih, bih, GI, MT, H3, Hh, 0);

    // persistent tensor-core GRU scan
    gru_scan<<<GRID_SCAN, 384>>>(GI, h0, WF, bhh, HS, HFa, HFb);

    // W3 on HS row-major (rows r = t*32+b)
    mma_gemm<<<dim3(Pp / 128, MT / 128), 256, 2 * MMSTG>>>(HS, W3, b3, S, MT, Pp, Hh, 1);

    head_kernel<<<6144, 256>>>(S, Wp, bp, label, out);
    copy_hlast<<<(Bb * Hh + 255) / 256, 256>>>(HS, out + Bb * Tt * 3);
}

// round 17
// speedup vs baseline: 1.1370x; 1.1370x over previous
#include <cuda_runtime.h>
#include <cuda_bf16.h>
#include <math.h>
#include <stdint.h>

#define Bb 32
#define Tt 512
#define Dd 512
#define Hh 2048
#define H3 6144
#define Pp 1024
#define MT (Bb*Tt)   // 16384
#define GRID_SCAN 128

typedef unsigned long long ull;

// ---------------- scratch ----------------------------------------------------------
__device__ float g_A1[(size_t)MT * 1024];
__device__ float g_A2[(size_t)MT * Hh];
__device__ float g_GI[(size_t)MT * H3];               // gi row-major (M,3H), r=b*T+t
__device__ float g_HS[(size_t)MT * Hh];               // h history ROW-MAJOR r=t*32+b
__device__ float g_S [(size_t)MT * Pp];
// W_hh fragment-packed: [blk(128)][nfg(3)][chunk(128)][frag(2)][lane(32)][4] + pad
__device__ __align__(256) uint32_t g_WF[(size_t)128 * 3 * 128 * 256 + 1024];
// h fragment ping-pong: [chunk(128)][frag(2)][hi 128 u32 | lo 128 u32] + pad
__device__ __align__(256) uint32_t g_HF[2][128 * 512 + 8 * 512];
__device__ unsigned g_bar_cnt;

// ---------------- helpers ----------------------------------------------------------
__device__ __forceinline__ float sigm(float x) { return 1.f / (1.f + expf(-x)); }
__device__ __forceinline__ uint32_t smem_u32(const void* p) {
    uint32_t a;
    asm("{ .reg .u64 t; cvta.to.shared.u64 t, %1; cvt.u32.u64 %0, t; }" : "=r"(a) : "l"(p));
    return a;
}
__device__ __forceinline__ void ldsm_x4(uint32_t* r, uint32_t addr) {
    asm volatile("ldmatrix.sync.aligned.m8n8.x4.shared.b16 {%0,%1,%2,%3}, [%4];"
                 : "=r"(r[0]), "=r"(r[1]), "=r"(r[2]), "=r"(r[3]) : "r"(addr));
}
__device__ __forceinline__ void ldsm_x2(uint32_t* r, uint32_t addr) {
    asm volatile("ldmatrix.sync.aligned.m8n8.x2.shared.b16 {%0,%1}, [%2];"
                 : "=r"(r[0]), "=r"(r[1]) : "r"(addr));
}
__device__ __forceinline__ void mma_bf16(float* c, const uint32_t* a, const uint32_t* b) {
    asm volatile("mma.sync.aligned.m16n8k16.row.col.f32.bf16.bf16.f32 "
                 "{%0,%1,%2,%3}, {%4,%5,%6,%7}, {%8,%9}, {%0,%1,%2,%3};"
                 : "+f"(c[0]), "+f"(c[1]), "+f"(c[2]), "+f"(c[3])
                 : "r"(a[0]), "r"(a[1]), "r"(a[2]), "r"(a[3]), "r"(b[0]), "r"(b[1]));
}
__device__ __forceinline__ void cvt_hilo(float x, float y, uint32_t& hi, uint32_t& lo) {
    __nv_bfloat16 hx = __float2bfloat16(x), hy = __float2bfloat16(y);
    float lx = x - __bfloat162float(hx), ly = y - __bfloat162float(hy);
    __nv_bfloat162 ph = __halves2bfloat162(hx, hy);
    __nv_bfloat162 pl = __halves2bfloat162(__float2bfloat16(lx), __float2bfloat16(ly));
    hi = *reinterpret_cast<uint32_t*>(&ph);
    lo = *reinterpret_cast<uint32_t*>(&pl);
}

// ---------------- split-bf16 mma.sync GEMM (proven R12/R13) ------------------------
#define MMROW 48
#define MMSTG 24576
__global__ __launch_bounds__(256)
void mma_gemm(const float* __restrict__ A, const float* __restrict__ B,
              const float* __restrict__ bias, float* __restrict__ C,
              int M, int N, int K, int doRelu)
{
    extern __shared__ char sm[];
    const uint32_t sbase = smem_u32(sm);
    const int tid  = threadIdx.x;
    const int wid  = tid >> 5;
    const int lane = tid & 31;
    const int wm   = wid & 1;
    const int wn   = wid >> 1;
    const int mb   = blockIdx.y, nb = blockIdx.x;

    const int srow = tid >> 2;
    const int scol = (tid & 3) * 4;
    const float* Ag = A + (size_t)(mb * 128 + srow) * K + scol;
    const float* Bg = B + (size_t)(nb * 128 + srow) * K + scol;
    const size_t g64 = (size_t)64 * K;

    float c[4][4][4];
#pragma unroll
    for (int i = 0; i < 4; i++)
#pragma unroll
        for (int j = 0; j < 4; j++)
#pragma unroll
            for (int q = 0; q < 4; q++) c[i][j][q] = 0.f;

    const int nk = K >> 4;
    float4 ra0, ra1, rb0, rb1;
    ra0 = *(const float4*)(Ag); ra1 = *(const float4*)(Ag + g64);
    rb0 = *(const float4*)(Bg); rb1 = *(const float4*)(Bg + g64);

    int buf = 0;
#define STORE_STAGE(BUF)                                                          \
    {                                                                             \
        uint32_t off = (BUF) * MMSTG;                                             \
        uint32_t h, l;                                                            \
        uint32_t a0 = off + srow * MMROW + scol * 2;                              \
        cvt_hilo(ra0.x, ra0.y, h, l);                                             \
        *(uint32_t*)(sm + a0)        = h; *(uint32_t*)(sm + a0 + 6144)     = l;   \
        cvt_hilo(ra0.z, ra0.w, h, l);                                             \
        *(uint32_t*)(sm + a0 + 4)    = h; *(uint32_t*)(sm + a0 + 6148)     = l;   \
        uint32_t a1 = a0 + 64 * MMROW;                                            \
        cvt_hilo(ra1.x, ra1.y, h, l);                                             \
        *(uint32_t*)(sm + a1)        = h; *(uint32_t*)(sm + a1 + 6144)     = l;   \
        cvt_hilo(ra1.z, ra1.w, h, l);                                             \
        *(uint32_t*)(sm + a1 + 4)    = h; *(uint32_t*)(sm + a1 + 6148)     = l;   \
        uint32_t b0 = off + 12288 + srow * MMROW + scol * 2;                      \
        cvt_hilo(rb0.x, rb0.y, h, l);                                             \
        *(uint32_t*)(sm + b0)        = h; *(uint32_t*)(sm + b0 + 6144)     = l;   \
        cvt_hilo(rb0.z, rb0.w, h, l);                                             \
        *(uint32_t*)(sm + b0 + 4)    = h; *(uint32_t*)(sm + b0 + 6148)     = l;   \
        uint32_t b1 = b0 + 64 * MMROW;                                            \
        cvt_hilo(rb1.x, rb1.y, h, l);                                             \
        *(uint32_t*)(sm + b1)        = h; *(uint32_t*)(sm + b1 + 6144)     = l;   \
        cvt_hilo(rb1.z, rb1.w, h, l);                                             \
        *(uint32_t*)(sm + b1 + 4)    = h; *(uint32_t*)(sm + b1 + 6148)     = l;   \
    }

    STORE_STAGE(0);
    __syncthreads();

    const uint32_t a_lrow = (uint32_t)(wm * 64 + (lane & 15)) * MMROW + ((lane >> 4) * 16);
    const uint32_t b_lrow = (uint32_t)(wn * 32 + (lane & 7)) * MMROW + (((lane >> 3) & 1) * 16);

    for (int kt = 0; kt < nk; kt++) {
        if (kt + 1 < nk) {
            const float* Agn = Ag + (kt + 1) * 16;
            const float* Bgn = Bg + (kt + 1) * 16;
            ra0 = *(const float4*)(Agn); ra1 = *(const float4*)(Agn + g64);
            rb0 = *(const float4*)(Bgn); rb1 = *(const float4*)(Bgn + g64);
        }
        const uint32_t off = buf * MMSTG;
        uint32_t ahi[4][4], alo[4][4];
#pragma unroll
        for (int mf = 0; mf < 4; mf++) {
            uint32_t ad = sbase + off + a_lrow + (uint32_t)mf * 16 * MMROW;
            ldsm_x4(ahi[mf], ad);
            ldsm_x4(alo[mf], ad + 6144);
        }
#pragma unroll
        for (int nf = 0; nf < 4; nf++) {
            uint32_t bd = sbase + off + 12288 + b_lrow + (uint32_t)nf * 8 * MMROW;
            uint32_t bhi[2], blo[2];
            ldsm_x2(bhi, bd);
            ldsm_x2(blo, bd + 6144);
#pragma unroll
            for (int mf = 0; mf < 4; mf++) {
                mma_bf16(c[mf][nf], ahi[mf], bhi);
                mma_bf16(c[mf][nf], ahi[mf], blo);
                mma_bf16(c[mf][nf], alo[mf], bhi);
            }
        }
        if (kt + 1 < nk) {
            STORE_STAGE(buf ^ 1);
            __syncthreads();
            buf ^= 1;
        }
    }
#undef STORE_STAGE

    const int rbase = mb * 128 + wm * 64 + (lane >> 2);
    const int cbase = nb * 128 + wn * 32 + 2 * (lane & 3);
#pragma unroll
    for (int mf = 0; mf < 4; mf++) {
#pragma unroll
        for (int nf = 0; nf < 4; nf++) {
            int col = cbase + nf * 8;
            float b0 = bias[col], b1 = bias[col + 1];
            float v0 = c[mf][nf][0] + b0, v1 = c[mf][nf][1] + b1;
            float v2 = c[mf][nf][2] + b0, v3 = c[mf][nf][3] + b1;
            if (doRelu) {
                v0 = fmaxf(v0, 0.f); v1 = fmaxf(v1, 0.f);
                v2 = fmaxf(v2, 0.f); v3 = fmaxf(v3, 0.f);
            }
            int r0 = rbase + mf * 16;
            *(float2*)(C + (size_t)r0 * N + col)       = make_float2(v0, v1);
            *(float2*)(C + (size_t)(r0 + 8) * N + col) = make_float2(v2, v3);
        }
    }
}

// ---------------- prepack W_hh: [blk][nfg][chunk][frag(2)] fragment stream ---------
__global__ __launch_bounds__(256)
void prepack_wf(const float* __restrict__ Whh, uint32_t* __restrict__ WF)
{
    int gw = blockIdx.x * 8 + (threadIdx.x >> 5);   // 0 .. 49151
    int lane = threadIdx.x & 31;
    int chunk = gw & 127;
    int rest  = gw >> 7;
    int nfg = rest % 3;
    int blk = rest / 3;
#pragma unroll
    for (int f = 0; f < 2; f++) {
        int j   = 2 * nfg + f;            // n-fragment 0..5
        int g   = j >> 1;
        int sub = j & 1;
        int n   = g * Hh + blk * 16 + sub * 8 + (lane >> 2);
        int k   = chunk * 16 + 2 * (lane & 3);
        const float* wr = Whh + (size_t)n * Hh + k;
        uint32_t bh0, bl0, bh1, bl1;
        cvt_hilo(wr[0], wr[1], bh0, bl0);
        cvt_hilo(wr[8], wr[9], bh1, bl1);
        uint32_t* o = WF + ((size_t)gw) * 256 + f * 128 + lane * 4;
        o[0] = bh0; o[1] = bh1; o[2] = bl0; o[3] = bl1;
    }
}

// ---------------- prepack h0 into A-fragment stream --------------------------------
__global__ __launch_bounds__(256)
void prepack_hf0(const float* __restrict__ h0, uint32_t* __restrict__ HF0)
{
    int gw = blockIdx.x * 8 + (threadIdx.x >> 5);   // 0..255
    int lane = threadIdx.x & 31;
    int c = gw >> 1, f = gw & 1;
    int b = f * 16 + (lane >> 2);
    int k = c * 16 + 2 * (lane & 3);
    const float* p0 = h0 + (size_t)b * Hh + k;
    const float* p1 = h0 + (size_t)(b + 8) * Hh + k;
    uint32_t h0r, l0r, h1r, l1r, h2r, l2r, h3r, l3r;
    cvt_hilo(p0[0], p0[1], h0r, l0r);
    cvt_hilo(p1[0], p1[1], h1r, l1r);
    cvt_hilo(p0[8], p0[9], h2r, l2r);
    cvt_hilo(p1[8], p1[9], h3r, l3r);
    uint32_t* o = HF0 + c * 512 + f * 256 + lane * 4;
    o[0] = h0r; o[1] = h1r; o[2] = h2r; o[3] = h3r;
    o[128] = l0r; o[129] = l1r; o[130] = l2r; o[131] = l3r;
}

__global__ void reset_bar() { g_bar_cnt = 0u; }

// ---------------- persistent mma GRU scan (3 nfg x 4 kq retile) --------------------
// 128 blocks x 384 threads. 12 warps = nfg(3: 2 n-frags each) x kq(4: 32 chunks each).
__global__ __launch_bounds__(384, 1)
void gru_scan(const float* __restrict__ gi0,     // row-major (M,3H), r=b*T+t
              const float* __restrict__ h0,      // (B, H)
              const uint32_t* __restrict__ WF,   // packed weights
              const float* __restrict__ bhh,
              float* __restrict__ HSrm,          // (M, H), r=t*32+b
              uint32_t* __restrict__ HFa,        // h frag ping-pong
              uint32_t* __restrict__ HFb)
{
    __shared__ float sred[4][6][32][8];           // 24 KB

    const int tid  = threadIdx.x;
    const int w    = tid >> 5;
    const int lane = tid & 31;
    const int nfg  = w % 3;
    const int kq   = w / 3;            // 0..3
    const int blk  = blockIdx.x;
    const int ch0  = kq * 32;

    const uint32_t* wstream =
        WF + ((size_t)(blk * 3 + nfg) * 128 + ch0) * 256 + lane * 4;

    const int ecol = tid >> 4;         // 0..15 (tid<256)
    const int ebp  = tid & 15;
    const int colg = blk * 16 + ecol;
    float br = 0.f, bz = 0.f, bn = 0.f;
    if (tid < 256) { br = bhh[colg]; bz = bhh[Hh + colg]; bn = bhh[2 * Hh + colg]; }

    for (int t = 0; t < Tt; t++) {
        const uint32_t* HFc = ((t & 1) ? HFb : HFa) + lane * 4;
        uint32_t*       HFn = (t & 1) ? HFa : HFb;

        // early epilogue-operand prefetch (consumed after the mainloop)
        float gi_r0 = 0.f, gi_r1 = 0.f, gi_z0 = 0.f, gi_z1 = 0.f;
        float gi_n0 = 0.f, gi_n1 = 0.f, hv0 = 0.f, hv1 = 0.f;
        if (tid < 256) {
            const int b0 = 2 * ebp, b1 = b0 + 1;
            const float* gr0 = gi0 + ((size_t)b0 * Tt + t) * H3 + colg;
            const float* gr1 = gi0 + ((size_t)b1 * Tt + t) * H3 + colg;
            gi_r0 = gr0[0];      gi_r1 = gr1[0];
            gi_z0 = gr0[Hh];     gi_z1 = gr1[Hh];
            gi_n0 = gr0[2 * Hh]; gi_n1 = gr1[2 * Hh];
            const float* hp0 = (t == 0) ? (h0 + (size_t)b0 * Hh)
                                        : (HSrm + ((size_t)(t - 1) * 32 + b0) * Hh);
            const float* hp1 = (t == 0) ? (h0 + (size_t)b1 * Hh)
                                        : (HSrm + ((size_t)(t - 1) * 32 + b1) * Hh);
            hv0 = hp0[colg]; hv1 = hp1[colg];
        }

        float cc[2][2][4];                 // [n-frag f][h-frag]
#pragma unroll
        for (int f = 0; f < 2; f++)
#pragma unroll
            for (int hf = 0; hf < 2; hf++)
#pragma unroll
                for (int q = 0; q < 4; q++) cc[f][hf][q] = 0.f;

        // rings: h depth 4 (4 x uint4), weights depth 4 x 2 frags
        uint4 rh[4][4];
        uint4 rw[4][2];
#pragma unroll
        for (int s = 0; s < 4; s++) {
            rh[s][0] = *(const uint4*)(HFc + (ch0 + s) * 512);
            rh[s][1] = *(const uint4*)(HFc + (ch0 + s) * 512 + 128);
            rh[s][2] = *(const uint4*)(HFc + (ch0 + s) * 512 + 256);
            rh[s][3] = *(const uint4*)(HFc + (ch0 + s) * 512 + 384);
            rw[s][0] = *(const uint4*)(wstream + (size_t)s * 256);
            rw[s][1] = *(const uint4*)(wstream + (size_t)s * 256 + 128);
        }

        for (int c = 0; c < 32; c += 4) {
#pragma unroll
            for (int u = 0; u < 4; u++) {
                uint4 ah0 = rh[u][0], al0 = rh[u][1];
                uint4 ah1 = rh[u][2], al1 = rh[u][3];
                uint4 w0  = rw[u][0], w1 = rw[u][1];
                const int cn = c + u + 4;            // refill (pads cover overrun)
                rh[u][0] = *(const uint4*)(HFc + (ch0 + cn) * 512);
                rh[u][1] = *(const uint4*)(HFc + (ch0 + cn) * 512 + 128);
                rh[u][2] = *(const uint4*)(HFc + (ch0 + cn) * 512 + 256);
                rh[u][3] = *(const uint4*)(HFc + (ch0 + cn) * 512 + 384);
                rw[u][0] = *(const uint4*)(wstream + (size_t)cn * 256);
                rw[u][1] = *(const uint4*)(wstream + (size_t)cn * 256 + 128);

                uint32_t bh0[2] = {w0.x, w0.y}, bl0w[2] = {w0.z, w0.w};
                uint32_t bh1[2] = {w1.x, w1.y}, bl1w[2] = {w1.z, w1.w};
                mma_bf16(cc[0][0], (const uint32_t*)&ah0, bh0);
                mma_bf16(cc[0][0], (const uint32_t*)&ah0, bl0w);
                mma_bf16(cc[0][0], (const uint32_t*)&al0, bh0);
                mma_bf16(cc[0][1], (const uint32_t*)&ah1, bh0);
                mma_bf16(cc[0][1], (const uint32_t*)&ah1, bl0w);
                mma_bf16(cc[0][1], (const uint32_t*)&al1, bh0);
                mma_bf16(cc[1][0], (const uint32_t*)&ah0, bh1);
                mma_bf16(cc[1][0], (const uint32_t*)&ah0, bl1w);
                mma_bf16(cc[1][0], (const uint32_t*)&al0, bh1);
                mma_bf16(cc[1][1], (const uint32_t*)&ah1, bh1);
                mma_bf16(cc[1][1], (const uint32_t*)&ah1, bl1w);
                mma_bf16(cc[1][1], (const uint32_t*)&al1, bh1);
            }
        }

        // store C fragments: rows = batches, cols = n within frag
#pragma unroll
        for (int f = 0; f < 2; f++) {
            float* sp = &sred[kq][2 * nfg + f][0][0];
            int r = lane >> 2, cb = 2 * (lane & 3);
            sp[r * 8 + cb]            = cc[f][0][0];
            sp[r * 8 + cb + 1]        = cc[f][0][1];
            sp[(r + 8) * 8 + cb]      = cc[f][0][2];
            sp[(r + 8) * 8 + cb + 1]  = cc[f][0][3];
            sp[(r + 16) * 8 + cb]     = cc[f][1][0];
            sp[(r + 16) * 8 + cb + 1] = cc[f][1][1];
            sp[(r + 24) * 8 + cb]     = cc[f][1][2];
            sp[(r + 24) * 8 + cb + 1] = cc[f][1][3];
        }
        __syncthreads();

        if (tid < 256) {
            const int nn = ecol & 7;
            const int b0 = 2 * ebp, b1 = b0 + 1;
            const int nfr = ecol >> 3;
            float ghr0 = 0.f, ghr1 = 0.f, ghz0 = 0.f, ghz1 = 0.f, ghn0 = 0.f, ghn1 = 0.f;
#pragma unroll
            for (int s = 0; s < 4; s++) {
                ghr0 += sred[s][0 + nfr][b0][nn];
                ghr1 += sred[s][0 + nfr][b1][nn];
                ghz0 += sred[s][2 + nfr][b0][nn];
                ghz1 += sred[s][2 + nfr][b1][nn];
                ghn0 += sred[s][4 + nfr][b0][nn];
                ghn1 += sred[s][4 + nfr][b1][nn];
            }

            float rx = sigm(gi_r0 + ghr0 + br);
            float ry = sigm(gi_r1 + ghr1 + br);
            float zx = sigm(gi_z0 + ghz0 + bz);
            float zy = sigm(gi_z1 + ghz1 + bz);
            float nx = tanhf(gi_n0 + rx * (ghn0 + bn));
            float ny = tanhf(gi_n1 + ry * (ghn1 + bn));
            float hn0 = (1.f - zx) * nx + zx * hv0;
            float hn1 = (1.f - zy) * ny + zy * hv1;

            HSrm[((size_t)t * 32 + b0) * Hh + colg] = hn0;
            HSrm[((size_t)t * 32 + b1) * Hh + colg] = hn1;

            // write h fragments for next step (bf16 hi/lo, scattered 2B)
            const int cch = colg >> 4, kk = colg & 15;
            const int lidx = ((kk >> 1) & 3);
#pragma unroll
            for (int bi = 0; bi < 2; bi++) {
                int b = b0 + bi;
                float hv = bi ? hn1 : hn0;
                int f = b >> 4, r = b & 15;
                int ln = ((r & 7) << 2) | lidx;
                int rg = ((r >> 3) & 1) | (((kk >> 3) & 1) << 1);
                int idx_hi = cch * 512 + f * 256 + ln * 4 + rg;
                __nv_bfloat16 hh = __float2bfloat16(hv);
                __nv_bfloat16 hl = __float2bfloat16(hv - __bfloat162float(hh));
                ((__nv_bfloat16*)HFn)[2 * idx_hi + (kk & 1)]         = hh;
                ((__nv_bfloat16*)HFn)[2 * (idx_hi + 128) + (kk & 1)] = hl;
            }
        }

        // -------- grid sync (R15 atomic version) --------
        __syncthreads();
        if (tid == 0) {
            __threadfence();
            atomicAdd(&g_bar_cnt, 1u);
            const unsigned target = (unsigned)(t + 1) * GRID_SCAN;
            unsigned v;
            do {
                asm volatile("ld.global.acquire.gpu.b32 %0, [%1];" : "=r"(v) : "l"(&g_bar_cnt));
                if (v >= target) break;
                __nanosleep(64);
            } while (true);
        }
        __syncthreads();
    }
}

// ---------------- head --------------------------------------------------------------
__global__ __launch_bounds__(256)
void head_kernel(const float* __restrict__ S, const float* __restrict__ Wp,
                 const float* __restrict__ bp, const int* __restrict__ label,
                 float* __restrict__ out)
{
    int w    = blockIdx.x * 8 + (threadIdx.x >> 5);
    int lane = threadIdx.x & 31;
    int bt = w / 3, j = w % 3;
    int t = bt >> 5, b = bt & 31;        // S row = t*32 + b
    int lab = label[b];
    const float* sp = S  + (size_t)bt * Pp;
    const float* wp = Wp + (size_t)(j * 8 + lab) * Pp;
    float sum = 0.f;
    for (int d = lane; d < Pp; d += 32)
        sum = fmaf(sp[d], wp[d], sum);
#pragma unroll
    for (int o = 16; o > 0; o >>= 1) sum += __shfl_xor_sync(0xffffffffu, sum, o);
    if (lane == 0)
        out[(size_t)b * Tt * 3 + t * 3 + j] = sum + bp[j * 8 + lab];
}

__global__ void copy_hlast(const float* __restrict__ HSrm, float* __restrict__ dst)
{
    int i = blockIdx.x * 256 + threadIdx.x;   // i = b*Hh + c
    if (i < Bb * Hh) {
        int b = i >> 11, c = i & (Hh - 1);
        dst[i] = HSrm[((size_t)(Tt - 1) * 32 + b) * Hh + c];
    }
}

// ---------------- launch ------------------------------------------------------------
extern "C" void kernel_launch(void* const* d_in, const int* in_sizes, int n_in,
                              void* d_out, int out_size)
{
    (void)in_sizes; (void)n_in; (void)out_size;
    const float* x     = (const float*)d_in[0];
    const int*   label = (const int*)  d_in[1];
    const float* h0    = (const float*)d_in[2];
    const float* W1  = (const float*)d_in[3];  const float* b1  = (const float*)d_in[4];
    const float* W2  = (const float*)d_in[5];  const float* b2  = (const float*)d_in[6];
    const float* Wih = (const float*)d_in[7];  const float* bih = (const float*)d_in[8];
    const float* Whh = (const float*)d_in[9];  const float* bhh = (const float*)d_in[10];
    const float* W3  = (const float*)d_in[11]; const float* b3  = (const float*)d_in[12];
    const float* Wp  = (const float*)d_in[13]; const float* bp  = (const float*)d_in[14];
    float* out = (float*)d_out;

    float *A1, *A2, *GI, *HS, *S;
    uint32_t *WF, *HF;
    cudaGetSymbolAddress((void**)&A1, g_A1);
    cudaGetSymbolAddress((void**)&A2, g_A2);
    cudaGetSymbolAddress((void**)&GI, g_GI);
    cudaGetSymbolAddress((void**)&HS, g_HS);
    cudaGetSymbolAddress((void**)&S,  g_S);
    cudaGetSymbolAddress((void**)&WF, g_WF);
    cudaGetSymbolAddress((void**)&HF, g_HF);
    uint32_t* HFa = HF;
    uint32_t* HFb = HF + (128 * 512 + 8 * 512);

    prepack_wf<<<49152 / 8, 256>>>(Whh, WF);
    prepack_hf0<<<256 / 8, 256>>>(h0, HFa);
    reset_bar<<<1, 1>>>();

    // all four big GEMMs on tensor cores (split-bf16, 3 passes)
    mma_gemm<<<dim3(1024 / 128, MT / 128), 256, 2 * MMSTG>>>(x,  W1, b1, A1, MT, 1024, Dd, 1);
    mma_gemm<<<dim3(Hh   / 128, MT / 128), 256, 2 * MMSTG>>>(A1, W2, b2, A2, MT, Hh, 1024, 1);
    mma_gemm<<<dim3(H3   / 128, MT / 128), 256, 2 * MMSTG>>>(A2, Wih, bih, GI, MT, H3, Hh, 0);

    // persistent tensor-core GRU scan
    gru_scan<<<GRID_SCAN, 384>>>(GI, h0, WF, bhh, HS, HFa, HFb);

    // W3 on HS row-major (rows r = t*32+b)
    mma_gemm<<<dim3(Pp / 128, MT / 128), 256, 2 * MMSTG>>>(HS, W3, b3, S, MT, Pp, Hh, 1);

    head_kernel<<<6144, 256>>>(S, Wp, bp, label, out);
    copy_hlast<<<(Bb * Hh + 255) / 256, 256>>>(HS, out + Bb * Tt * 3);
}